// round 10
// baseline (speedup 1.0000x reference)
#include <cuda_runtime.h>
#include <math.h>
#include <stdint.h>

// Problem constants
#define Bq  2
#define Sq  2048
#define Dq  1024
#define Hq  16
#define HDq 64

__device__ float g_qkv[(size_t)Bq * Sq * 3 * Dq];   // (B,S,3D)
__device__ float g_vals[(size_t)Bq * Sq * Dq];      // (B,S,D)

// ---------------------------------------------------------------------------
// tf32 helpers
// ---------------------------------------------------------------------------
__device__ __forceinline__ uint32_t f2tf32(float x) {
    uint32_t r;
    asm("cvt.rna.tf32.f32 %0, %1;" : "=r"(r) : "f"(x));
    return r;
}

__device__ __forceinline__ void mma_tf32(float c[4],
                                         uint32_t a0, uint32_t a1, uint32_t a2, uint32_t a3,
                                         uint32_t b0, uint32_t b1) {
    asm volatile(
        "mma.sync.aligned.m16n8k8.row.col.f32.tf32.tf32.f32 "
        "{%0,%1,%2,%3}, {%4,%5,%6,%7}, {%8,%9}, {%0,%1,%2,%3};"
        : "+f"(c[0]), "+f"(c[1]), "+f"(c[2]), "+f"(c[3])
        : "r"(a0), "r"(a1), "r"(a2), "r"(a3), "r"(b0), "r"(b1));
}

// ---------------------------------------------------------------------------
// tf32 GEMM: C[M,N] = A[M,K] @ W[N,K]^T + bias[N]
// (verbatim round-2/9 kernel — measured best of all loader variants)
// ---------------------------------------------------------------------------
__global__ void __launch_bounds__(256)
gemm_tf32_nt_bias(int M, int N, int K,
                  const float* __restrict__ A,
                  const float* __restrict__ W,
                  const float* __restrict__ bias,
                  float* __restrict__ C)
{
    constexpr int BK = 32, PITCH = 36;
    __shared__ uint32_t As[128][PITCH];
    __shared__ uint32_t Ws[128][PITCH];

    const int tid  = threadIdx.x;
    const int lane = tid & 31;
    const int w    = tid >> 5;
    const int wr   = w >> 2;      // 0..1
    const int wc   = w & 3;       // 0..3
    const int m0   = blockIdx.y * 128;
    const int n0   = blockIdx.x * 128;

    const int g  = lane >> 2;     // groupID 0..7
    const int tq = lane & 3;      // threadID in quad 0..3

    float acc[4][4][4];
#pragma unroll
    for (int i = 0; i < 4; i++)
#pragma unroll
        for (int j = 0; j < 4; j++)
#pragma unroll
            for (int e = 0; e < 4; e++) acc[i][j][e] = 0.0f;

    const int lrow = tid >> 3;          // 0..31
    const int lc4  = (tid & 7) << 2;    // 0..28

    for (int k0 = 0; k0 < K; k0 += BK) {
#pragma unroll
        for (int rr = 0; rr < 4; rr++) {
            const int r = lrow + rr * 32;
            float4 av = *(const float4*)(A + (size_t)(m0 + r) * K + k0 + lc4);
            As[r][lc4 + 0] = f2tf32(av.x); As[r][lc4 + 1] = f2tf32(av.y);
            As[r][lc4 + 2] = f2tf32(av.z); As[r][lc4 + 3] = f2tf32(av.w);
            float4 wv = *(const float4*)(W + (size_t)(n0 + r) * K + k0 + lc4);
            Ws[r][lc4 + 0] = f2tf32(wv.x); Ws[r][lc4 + 1] = f2tf32(wv.y);
            Ws[r][lc4 + 2] = f2tf32(wv.z); Ws[r][lc4 + 3] = f2tf32(wv.w);
        }
        __syncthreads();

#pragma unroll
        for (int ks = 0; ks < 4; ks++) {
            const int kk = ks * 8;
            uint32_t af[4][4];
#pragma unroll
            for (int mi = 0; mi < 4; mi++) {
                const int rb = wr * 64 + mi * 16;
                af[mi][0] = As[rb + g    ][kk + tq    ];
                af[mi][1] = As[rb + g + 8][kk + tq    ];
                af[mi][2] = As[rb + g    ][kk + tq + 4];
                af[mi][3] = As[rb + g + 8][kk + tq + 4];
            }
            uint32_t bf[4][2];
#pragma unroll
            for (int ni = 0; ni < 4; ni++) {
                const int cb = wc * 32 + ni * 8;
                bf[ni][0] = Ws[cb + g][kk + tq    ];
                bf[ni][1] = Ws[cb + g][kk + tq + 4];
            }
#pragma unroll
            for (int mi = 0; mi < 4; mi++)
#pragma unroll
                for (int ni = 0; ni < 4; ni++)
                    mma_tf32(acc[mi][ni],
                             af[mi][0], af[mi][1], af[mi][2], af[mi][3],
                             bf[ni][0], bf[ni][1]);
        }
        __syncthreads();
    }

#pragma unroll
    for (int mi = 0; mi < 4; mi++) {
        const int r0 = m0 + wr * 64 + mi * 16 + g;
#pragma unroll
        for (int ni = 0; ni < 4; ni++) {
            const int c = n0 + wc * 32 + ni * 8 + 2 * tq;
            const float b0v = bias[c], b1v = bias[c + 1];
            float2 o0 = make_float2(acc[mi][ni][0] + b0v, acc[mi][ni][1] + b1v);
            float2 o1 = make_float2(acc[mi][ni][2] + b0v, acc[mi][ni][3] + b1v);
            *(float2*)(C + (size_t)r0 * N + c)       = o0;
            *(float2*)(C + (size_t)(r0 + 8) * N + c) = o1;
        }
    }
}

// ---------------------------------------------------------------------------
// Flash attention, tf32. Grid (S/64, H, B), 128 threads (4 warps), 4 CTAs/SM.
// Round-10 changes vs round-9 (same smem total, 53248 B):
//  - Q fragments register-resident (extracted once in prologue)
//  - Q's smem slot becomes the dedicated P buffer -> P-stash needs only
//    __syncwarp; block barriers per k-tile: 3 -> 2.
//  - softmax computed in place in Sacc (register economy).
// ---------------------------------------------------------------------------
#define QP 68
#define VP 72

__global__ void __launch_bounds__(128, 4)
flash_attn_tf32(const float* __restrict__ qkv,
                const float* __restrict__ mask,
                float* __restrict__ out)
{
    extern __shared__ uint32_t sm[];
    uint32_t* Ps = sm;                  // [64][QP]  Q staging, then P
    uint32_t* Ks = sm + 64 * QP;        // [64][QP]
    uint32_t* Vs = sm + 2 * 64 * QP;    // [64][VP]

    const int tid  = threadIdx.x;
    const int lane = tid & 31;
    const int wid  = tid >> 5;     // 0..3 -> q rows [wid*16, +16)
    const int g    = lane >> 2;    // 0..7
    const int tq   = lane & 3;     // 0..3

    const int q0 = blockIdx.x * 64;
    const int h  = blockIdx.y;
    const int b  = blockIdx.z;
    const float scale = 0.125f;

    const float* base = qkv + (size_t)b * Sq * (3 * Dq) + (size_t)h * (3 * HDq);

    // ---- stage Q tile (64 x 64) as tf32 into Ps ----
#pragma unroll
    for (int rr = 0; rr < 8; rr++) {
        const int r  = (tid >> 4) + rr * 8;
        const int c4 = (tid & 15) << 2;
        float4 v = *(const float4*)(base + (size_t)(q0 + r) * (3 * Dq) + c4);
        Ps[r * QP + c4 + 0] = f2tf32(v.x);
        Ps[r * QP + c4 + 1] = f2tf32(v.y);
        Ps[r * QP + c4 + 2] = f2tf32(v.z);
        Ps[r * QP + c4 + 3] = f2tf32(v.w);
    }
    __syncthreads();

    // ---- extract Q fragments into registers (reused all k-tiles) ----
    uint32_t qa[8][4];
    {
        const int mb = wid * 16;
#pragma unroll
        for (int ks = 0; ks < 8; ks++) {
            const int kk = ks * 8;
            qa[ks][0] = Ps[(mb + g)     * QP + kk + tq];
            qa[ks][1] = Ps[(mb + g + 8) * QP + kk + tq];
            qa[ks][2] = Ps[(mb + g)     * QP + kk + tq + 4];
            qa[ks][3] = Ps[(mb + g + 8) * QP + kk + tq + 4];
        }
    }
    __syncthreads();   // everyone done reading Q; Ps free for P use

    float Oacc[8][4];
#pragma unroll
    for (int ni = 0; ni < 8; ni++)
#pragma unroll
        for (int e = 0; e < 4; e++) Oacc[ni][e] = 0.0f;
    float mrow0 = -INFINITY, mrow1 = -INFINITY;
    float lrow0 = 0.0f, lrow1 = 0.0f;

    const int r0 = wid * 16 + g;   // this thread's first q row (within tile)
    const int r1 = r0 + 8;

    for (int kt = 0; kt < Sq / 64; kt++) {
        const int k0t = kt * 64;

        // ---- load K and V tiles ----
#pragma unroll
        for (int rr = 0; rr < 8; rr++) {
            const int r  = (tid >> 4) + rr * 8;
            const int c4 = (tid & 15) << 2;
            float4 kv = *(const float4*)(base + 64 + (size_t)(k0t + r) * (3 * Dq) + c4);
            Ks[r * QP + c4 + 0] = f2tf32(kv.x);
            Ks[r * QP + c4 + 1] = f2tf32(kv.y);
            Ks[r * QP + c4 + 2] = f2tf32(kv.z);
            Ks[r * QP + c4 + 3] = f2tf32(kv.w);
            float4 vv = *(const float4*)(base + 128 + (size_t)(k0t + r) * (3 * Dq) + c4);
            Vs[r * VP + c4 + 0] = f2tf32(vv.x);
            Vs[r * VP + c4 + 1] = f2tf32(vv.y);
            Vs[r * VP + c4 + 2] = f2tf32(vv.z);
            Vs[r * VP + c4 + 3] = f2tf32(vv.w);
        }
        __syncthreads();   // (B) K/V visible

        // ---- S = Q K^T : warp computes 16 x 64 ----
        float Sacc[8][4];
#pragma unroll
        for (int ni = 0; ni < 8; ni++)
#pragma unroll
            for (int e = 0; e < 4; e++) Sacc[ni][e] = 0.0f;

#pragma unroll
        for (int ks = 0; ks < 8; ks++) {
            const int kk = ks * 8;
#pragma unroll
            for (int ni = 0; ni < 8; ni++) {
                const int nb = ni * 8;
                uint32_t b0 = Ks[(nb + g) * QP + kk + tq];
                uint32_t b1 = Ks[(nb + g) * QP + kk + tq + 4];
                mma_tf32(Sacc[ni], qa[ks][0], qa[ks][1], qa[ks][2], qa[ks][3], b0, b1);
            }
        }

        // ---- scale + mask + online softmax (in place) ----
        float rmax0 = -INFINITY, rmax1 = -INFINITY;
#pragma unroll
        for (int ni = 0; ni < 8; ni++) {
            const int c = ni * 8 + 2 * tq;
            float2 mk0 = *(const float2*)(mask + (size_t)(q0 + r0) * Sq + k0t + c);
            float2 mk1 = *(const float2*)(mask + (size_t)(q0 + r1) * Sq + k0t + c);
            Sacc[ni][0] = Sacc[ni][0] * scale + mk0.x;
            Sacc[ni][1] = Sacc[ni][1] * scale + mk0.y;
            Sacc[ni][2] = Sacc[ni][2] * scale + mk1.x;
            Sacc[ni][3] = Sacc[ni][3] * scale + mk1.y;
            rmax0 = fmaxf(rmax0, fmaxf(Sacc[ni][0], Sacc[ni][1]));
            rmax1 = fmaxf(rmax1, fmaxf(Sacc[ni][2], Sacc[ni][3]));
        }
#pragma unroll
        for (int off = 1; off < 4; off <<= 1) {
            rmax0 = fmaxf(rmax0, __shfl_xor_sync(0xffffffffu, rmax0, off));
            rmax1 = fmaxf(rmax1, __shfl_xor_sync(0xffffffffu, rmax1, off));
        }
        const float mnew0 = fmaxf(mrow0, rmax0);
        const float mnew1 = fmaxf(mrow1, rmax1);
        const float alpha0 = __expf(mrow0 - mnew0);
        const float alpha1 = __expf(mrow1 - mnew1);
        float rs0 = 0.0f, rs1 = 0.0f;
#pragma unroll
        for (int ni = 0; ni < 8; ni++) {
            Sacc[ni][0] = __expf(Sacc[ni][0] - mnew0);
            Sacc[ni][1] = __expf(Sacc[ni][1] - mnew0);
            Sacc[ni][2] = __expf(Sacc[ni][2] - mnew1);
            Sacc[ni][3] = __expf(Sacc[ni][3] - mnew1);
            rs0 += Sacc[ni][0] + Sacc[ni][1];
            rs1 += Sacc[ni][2] + Sacc[ni][3];
        }
#pragma unroll
        for (int off = 1; off < 4; off <<= 1) {
            rs0 += __shfl_xor_sync(0xffffffffu, rs0, off);
            rs1 += __shfl_xor_sync(0xffffffffu, rs1, off);
        }
        lrow0 = lrow0 * alpha0 + rs0;
        lrow1 = lrow1 * alpha1 + rs1;
        mrow0 = mnew0;
        mrow1 = mnew1;
#pragma unroll
        for (int ni = 0; ni < 8; ni++) {
            Oacc[ni][0] *= alpha0; Oacc[ni][1] *= alpha0;
            Oacc[ni][2] *= alpha1; Oacc[ni][3] *= alpha1;
        }

        // ---- stash P (tf32) into this warp's private rows of Ps ----
        const int qr0 = wid * 16 + g;
#pragma unroll
        for (int ni = 0; ni < 8; ni++) {
            const int c = ni * 8 + 2 * tq;
            uint2 s0 = make_uint2(f2tf32(Sacc[ni][0]), f2tf32(Sacc[ni][1]));
            uint2 s1 = make_uint2(f2tf32(Sacc[ni][2]), f2tf32(Sacc[ni][3]));
            *(uint2*)(Ps + (qr0)     * QP + c) = s0;
            *(uint2*)(Ps + (qr0 + 8) * QP + c) = s1;
        }
        __syncwarp();

        // ---- O += P V ----
#pragma unroll
        for (int ks = 0; ks < 8; ks++) {
            const int kk = ks * 8;
            const int mb = wid * 16;
            uint32_t a0 = Ps[(mb + g)     * QP + kk + tq];
            uint32_t a1 = Ps[(mb + g + 8) * QP + kk + tq];
            uint32_t a2 = Ps[(mb + g)     * QP + kk + tq + 4];
            uint32_t a3 = Ps[(mb + g + 8) * QP + kk + tq + 4];
#pragma unroll
            for (int ni = 0; ni < 8; ni++) {
                const int nb = ni * 8;
                uint32_t b0 = Vs[(kk + tq)     * VP + nb + g];
                uint32_t b1 = Vs[(kk + tq + 4) * VP + nb + g];
                mma_tf32(Oacc[ni], a0, a1, a2, a3, b0, b1);
            }
        }

        __syncthreads();   // (A) all warps done reading Ks/Vs before next load
    }

    // ---- epilogue ----
    const float inv0 = 1.0f / lrow0;
    const float inv1 = 1.0f / lrow1;
    float* obase = out + (size_t)b * Sq * Dq + (size_t)h * HDq;
#pragma unroll
    for (int ni = 0; ni < 8; ni++) {
        const int c = ni * 8 + 2 * tq;
        float2 o0 = make_float2(Oacc[ni][0] * inv0, Oacc[ni][1] * inv0);
        float2 o1 = make_float2(Oacc[ni][2] * inv1, Oacc[ni][3] * inv1);
        *(float2*)(obase + (size_t)(q0 + r0) * Dq + c) = o0;
        *(float2*)(obase + (size_t)(q0 + r1) * Dq + c) = o1;
    }
}

// ---------------------------------------------------------------------------
extern "C" void kernel_launch(void* const* d_in, const int* in_sizes, int n_in,
                              void* d_out, int out_size)
{
    const float* x    = (const float*)d_in[0];
    const float* mask = (const float*)d_in[1];
    const float* Wqkv = (const float*)d_in[2];
    const float* bqkv = (const float*)d_in[3];
    const float* Wo   = (const float*)d_in[4];
    const float* bo   = (const float*)d_in[5];
    float* out = (float*)d_out;

    float* qkv  = nullptr;
    float* vals = nullptr;
    cudaGetSymbolAddress((void**)&qkv,  g_qkv);
    cudaGetSymbolAddress((void**)&vals, g_vals);

    // 1) QKV projection
    {
        dim3 grid((3 * Dq) / 128, (Bq * Sq) / 128);
        gemm_tf32_nt_bias<<<grid, 256>>>(Bq * Sq, 3 * Dq, Dq, x, Wqkv, bqkv, qkv);
    }

    // 2) Flash attention (tf32 mma, 53KB smem, 4 CTAs/SM, 2 barriers/tile)
    {
        const int smem = (2 * 64 * QP + 64 * VP) * (int)sizeof(uint32_t); // 53248 B
        cudaFuncSetAttribute(flash_attn_tf32,
                             cudaFuncAttributeMaxDynamicSharedMemorySize, smem);
        dim3 grid(Sq / 64, Hq, Bq);
        flash_attn_tf32<<<grid, 128, smem>>>(qkv, mask, vals);
    }

    // 3) Output projection
    {
        dim3 grid(Dq / 128, (Bq * Sq) / 128);
        gemm_tf32_nt_bias<<<grid, 256>>>(Bq * Sq, Dq, Dq, vals, Wo, bo, out);
    }
}

// round 11
// speedup vs baseline: 1.0840x; 1.0840x over previous
#include <cuda_runtime.h>
#include <math.h>
#include <stdint.h>

// Problem constants
#define Bq  2
#define Sq  2048
#define Dq  1024
#define Hq  16
#define HDq 64

__device__ float g_qkv[(size_t)Bq * Sq * 3 * Dq];   // (B,S,3D), tf32-rounded
__device__ float g_vals[(size_t)Bq * Sq * Dq];      // (B,S,D)

// ---------------------------------------------------------------------------
// tf32 helpers
// ---------------------------------------------------------------------------
__device__ __forceinline__ uint32_t f2tf32(float x) {
    uint32_t r;
    asm("cvt.rna.tf32.f32 %0, %1;" : "=r"(r) : "f"(x));
    return r;
}
__device__ __forceinline__ float roundtf(float x) {
    return __uint_as_float(f2tf32(x));
}

__device__ __forceinline__ void mma_tf32(float c[4],
                                         uint32_t a0, uint32_t a1, uint32_t a2, uint32_t a3,
                                         uint32_t b0, uint32_t b1) {
    asm volatile(
        "mma.sync.aligned.m16n8k8.row.col.f32.tf32.tf32.f32 "
        "{%0,%1,%2,%3}, {%4,%5,%6,%7}, {%8,%9}, {%0,%1,%2,%3};"
        : "+f"(c[0]), "+f"(c[1]), "+f"(c[2]), "+f"(c[3])
        : "r"(a0), "r"(a1), "r"(a2), "r"(a3), "r"(b0), "r"(b1));
}

// ---------------------------------------------------------------------------
// tf32 GEMM: C[M,N] = A[M,K] @ W[N,K]^T + bias[N]
// (verbatim round-2/9 kernel, plus optional tf32-rounded epilogue)
// ---------------------------------------------------------------------------
template <bool ROUND>
__global__ void __launch_bounds__(256)
gemm_tf32_nt_bias(int M, int N, int K,
                  const float* __restrict__ A,
                  const float* __restrict__ W,
                  const float* __restrict__ bias,
                  float* __restrict__ C)
{
    constexpr int BK = 32, PITCH = 36;
    __shared__ uint32_t As[128][PITCH];
    __shared__ uint32_t Ws[128][PITCH];

    const int tid  = threadIdx.x;
    const int lane = tid & 31;
    const int w    = tid >> 5;
    const int wr   = w >> 2;      // 0..1
    const int wc   = w & 3;       // 0..3
    const int m0   = blockIdx.y * 128;
    const int n0   = blockIdx.x * 128;

    const int g  = lane >> 2;     // groupID 0..7
    const int tq = lane & 3;      // threadID in quad 0..3

    float acc[4][4][4];
#pragma unroll
    for (int i = 0; i < 4; i++)
#pragma unroll
        for (int j = 0; j < 4; j++)
#pragma unroll
            for (int e = 0; e < 4; e++) acc[i][j][e] = 0.0f;

    const int lrow = tid >> 3;          // 0..31
    const int lc4  = (tid & 7) << 2;    // 0..28

    for (int k0 = 0; k0 < K; k0 += BK) {
#pragma unroll
        for (int rr = 0; rr < 4; rr++) {
            const int r = lrow + rr * 32;
            float4 av = *(const float4*)(A + (size_t)(m0 + r) * K + k0 + lc4);
            As[r][lc4 + 0] = f2tf32(av.x); As[r][lc4 + 1] = f2tf32(av.y);
            As[r][lc4 + 2] = f2tf32(av.z); As[r][lc4 + 3] = f2tf32(av.w);
            float4 wv = *(const float4*)(W + (size_t)(n0 + r) * K + k0 + lc4);
            Ws[r][lc4 + 0] = f2tf32(wv.x); Ws[r][lc4 + 1] = f2tf32(wv.y);
            Ws[r][lc4 + 2] = f2tf32(wv.z); Ws[r][lc4 + 3] = f2tf32(wv.w);
        }
        __syncthreads();

#pragma unroll
        for (int ks = 0; ks < 4; ks++) {
            const int kk = ks * 8;
            uint32_t af[4][4];
#pragma unroll
            for (int mi = 0; mi < 4; mi++) {
                const int rb = wr * 64 + mi * 16;
                af[mi][0] = As[rb + g    ][kk + tq    ];
                af[mi][1] = As[rb + g + 8][kk + tq    ];
                af[mi][2] = As[rb + g    ][kk + tq + 4];
                af[mi][3] = As[rb + g + 8][kk + tq + 4];
            }
            uint32_t bf[4][2];
#pragma unroll
            for (int ni = 0; ni < 4; ni++) {
                const int cb = wc * 32 + ni * 8;
                bf[ni][0] = Ws[cb + g][kk + tq    ];
                bf[ni][1] = Ws[cb + g][kk + tq + 4];
            }
#pragma unroll
            for (int mi = 0; mi < 4; mi++)
#pragma unroll
                for (int ni = 0; ni < 4; ni++)
                    mma_tf32(acc[mi][ni],
                             af[mi][0], af[mi][1], af[mi][2], af[mi][3],
                             bf[ni][0], bf[ni][1]);
        }
        __syncthreads();
    }

#pragma unroll
    for (int mi = 0; mi < 4; mi++) {
        const int r0 = m0 + wr * 64 + mi * 16 + g;
#pragma unroll
        for (int ni = 0; ni < 4; ni++) {
            const int c = n0 + wc * 32 + ni * 8 + 2 * tq;
            const float b0v = bias[c], b1v = bias[c + 1];
            float2 o0, o1;
            if (ROUND) {
                o0 = make_float2(roundtf(acc[mi][ni][0] + b0v), roundtf(acc[mi][ni][1] + b1v));
                o1 = make_float2(roundtf(acc[mi][ni][2] + b0v), roundtf(acc[mi][ni][3] + b1v));
            } else {
                o0 = make_float2(acc[mi][ni][0] + b0v, acc[mi][ni][1] + b1v);
                o1 = make_float2(acc[mi][ni][2] + b0v, acc[mi][ni][3] + b1v);
            }
            *(float2*)(C + (size_t)r0 * N + c)       = o0;
            *(float2*)(C + (size_t)(r0 + 8) * N + c) = o1;
        }
    }
}

// ---------------------------------------------------------------------------
// Flash attention, tf32. Grid (S/64, H, B), 128 threads (4 warps), 4 CTAs/SM.
// Structure identical to the proven round-9 kernel; qkv is pre-rounded to
// tf32 by the QKV GEMM epilogue, so Q/K/V tile loads are raw uint4 copies
// (no cvt, vectorized STS.128).  smem 53248 B.
// ---------------------------------------------------------------------------
#define QP 68
#define VP 72

__global__ void __launch_bounds__(128, 4)
flash_attn_tf32(const float* __restrict__ qkv,
                const float* __restrict__ mask,
                float* __restrict__ out)
{
    extern __shared__ uint32_t sm[];
    uint32_t* Qs = sm;                  // [64][QP]  (persistent)
    uint32_t* Ks = sm + 64 * QP;        // [64][QP]  (doubles as P after S-phase)
    uint32_t* Vs = sm + 2 * 64 * QP;    // [64][VP]

    const int tid  = threadIdx.x;
    const int lane = tid & 31;
    const int wid  = tid >> 5;     // 0..3 -> q rows [wid*16, +16)
    const int g    = lane >> 2;    // 0..7
    const int tq   = lane & 3;     // 0..3

    const int q0 = blockIdx.x * 64;
    const int h  = blockIdx.y;
    const int b  = blockIdx.z;
    const float scale = 0.125f;

    const uint32_t* base =
        (const uint32_t*)(qkv + (size_t)b * Sq * (3 * Dq) + (size_t)h * (3 * HDq));

    // Load Q tile (64 x 64), already tf32-rounded -> raw copy
#pragma unroll
    for (int rr = 0; rr < 8; rr++) {
        const int r  = (tid >> 4) + rr * 8;
        const int c4 = (tid & 15) << 2;
        uint4 v = *(const uint4*)(base + (size_t)(q0 + r) * (3 * Dq) + c4);
        *(uint4*)(Qs + r * QP + c4) = v;
    }

    float Oacc[8][4];
#pragma unroll
    for (int ni = 0; ni < 8; ni++)
#pragma unroll
        for (int e = 0; e < 4; e++) Oacc[ni][e] = 0.0f;
    float mrow0 = -INFINITY, mrow1 = -INFINITY;
    float lrow0 = 0.0f, lrow1 = 0.0f;

    const int r0 = wid * 16 + g;   // this thread's first q row (within tile)
    const int r1 = r0 + 8;

    for (int kt = 0; kt < Sq / 64; kt++) {
        const int k0t = kt * 64;
        __syncthreads();   // prev PV done reading Ks(P)/Vs; Q visible on 1st iter

        // Load K and V tiles (pre-rounded) -> raw uint4 copies
#pragma unroll
        for (int rr = 0; rr < 8; rr++) {
            const int r  = (tid >> 4) + rr * 8;
            const int c4 = (tid & 15) << 2;
            uint4 kv = *(const uint4*)(base + 64 + (size_t)(k0t + r) * (3 * Dq) + c4);
            *(uint4*)(Ks + r * QP + c4) = kv;
            uint4 vv = *(const uint4*)(base + 128 + (size_t)(k0t + r) * (3 * Dq) + c4);
            *(uint4*)(Vs + r * VP + c4) = vv;
        }
        __syncthreads();

        // S = Q K^T : warp computes 16 x 64 (8 n-tiles)
        float Sacc[8][4];
#pragma unroll
        for (int ni = 0; ni < 8; ni++)
#pragma unroll
            for (int e = 0; e < 4; e++) Sacc[ni][e] = 0.0f;

#pragma unroll
        for (int ks = 0; ks < 8; ks++) {
            const int kk = ks * 8;
            const int mb = wid * 16;
            uint32_t a0 = Qs[(mb + g)     * QP + kk + tq];
            uint32_t a1 = Qs[(mb + g + 8) * QP + kk + tq];
            uint32_t a2 = Qs[(mb + g)     * QP + kk + tq + 4];
            uint32_t a3 = Qs[(mb + g + 8) * QP + kk + tq + 4];
#pragma unroll
            for (int ni = 0; ni < 8; ni++) {
                const int nb = ni * 8;
                uint32_t b0 = Ks[(nb + g) * QP + kk + tq];
                uint32_t b1 = Ks[(nb + g) * QP + kk + tq + 4];
                mma_tf32(Sacc[ni], a0, a1, a2, a3, b0, b1);
            }
        }

        // scale + mask + online softmax (rows r0, r1; cols 8*ni + 2*tq {,+1})
        float p0[8][2], p1[8][2];
        float rmax0 = -INFINITY, rmax1 = -INFINITY;
#pragma unroll
        for (int ni = 0; ni < 8; ni++) {
            const int c = ni * 8 + 2 * tq;
            float2 mk0 = *(const float2*)(mask + (size_t)(q0 + r0) * Sq + k0t + c);
            float2 mk1 = *(const float2*)(mask + (size_t)(q0 + r1) * Sq + k0t + c);
            p0[ni][0] = Sacc[ni][0] * scale + mk0.x;
            p0[ni][1] = Sacc[ni][1] * scale + mk0.y;
            p1[ni][0] = Sacc[ni][2] * scale + mk1.x;
            p1[ni][1] = Sacc[ni][3] * scale + mk1.y;
            rmax0 = fmaxf(rmax0, fmaxf(p0[ni][0], p0[ni][1]));
            rmax1 = fmaxf(rmax1, fmaxf(p1[ni][0], p1[ni][1]));
        }
#pragma unroll
        for (int off = 1; off < 4; off <<= 1) {
            rmax0 = fmaxf(rmax0, __shfl_xor_sync(0xffffffffu, rmax0, off));
            rmax1 = fmaxf(rmax1, __shfl_xor_sync(0xffffffffu, rmax1, off));
        }
        const float mnew0 = fmaxf(mrow0, rmax0);
        const float mnew1 = fmaxf(mrow1, rmax1);
        const float alpha0 = __expf(mrow0 - mnew0);
        const float alpha1 = __expf(mrow1 - mnew1);
        float rs0 = 0.0f, rs1 = 0.0f;
#pragma unroll
        for (int ni = 0; ni < 8; ni++) {
            p0[ni][0] = __expf(p0[ni][0] - mnew0);
            p0[ni][1] = __expf(p0[ni][1] - mnew0);
            p1[ni][0] = __expf(p1[ni][0] - mnew1);
            p1[ni][1] = __expf(p1[ni][1] - mnew1);
            rs0 += p0[ni][0] + p0[ni][1];
            rs1 += p1[ni][0] + p1[ni][1];
        }
#pragma unroll
        for (int off = 1; off < 4; off <<= 1) {
            rs0 += __shfl_xor_sync(0xffffffffu, rs0, off);
            rs1 += __shfl_xor_sync(0xffffffffu, rs1, off);
        }
        lrow0 = lrow0 * alpha0 + rs0;
        lrow1 = lrow1 * alpha1 + rs1;
        mrow0 = mnew0;
        mrow1 = mnew1;
#pragma unroll
        for (int ni = 0; ni < 8; ni++) {
            Oacc[ni][0] *= alpha0; Oacc[ni][1] *= alpha0;
            Oacc[ni][2] *= alpha1; Oacc[ni][3] *= alpha1;
        }

        // All warps finished reading Ks in the S phase -> Ks reusable as P
        __syncthreads();

        // stash P (tf32) into this warp's private rows of Ks
        const int qr0 = wid * 16 + g;
#pragma unroll
        for (int ni = 0; ni < 8; ni++) {
            const int c = ni * 8 + 2 * tq;
            uint2 s0 = make_uint2(f2tf32(p0[ni][0]), f2tf32(p0[ni][1]));
            uint2 s1 = make_uint2(f2tf32(p1[ni][0]), f2tf32(p1[ni][1]));
            *(uint2*)(Ks + (qr0)     * QP + c) = s0;
            *(uint2*)(Ks + (qr0 + 8) * QP + c) = s1;
        }
        __syncwarp();

        // O += P V : A = Ks-as-P (16 x 64 keys), B = Vs (keys x hd)
#pragma unroll
        for (int ks = 0; ks < 8; ks++) {
            const int kk = ks * 8;
            const int mb = wid * 16;
            uint32_t a0 = Ks[(mb + g)     * QP + kk + tq];
            uint32_t a1 = Ks[(mb + g + 8) * QP + kk + tq];
            uint32_t a2 = Ks[(mb + g)     * QP + kk + tq + 4];
            uint32_t a3 = Ks[(mb + g + 8) * QP + kk + tq + 4];
#pragma unroll
            for (int ni = 0; ni < 8; ni++) {
                const int nb = ni * 8;
                uint32_t b0 = Vs[(kk + tq)     * VP + nb + g];
                uint32_t b1 = Vs[(kk + tq + 4) * VP + nb + g];
                mma_tf32(Oacc[ni], a0, a1, a2, a3, b0, b1);
            }
        }
    }

    // Epilogue
    const float inv0 = 1.0f / lrow0;
    const float inv1 = 1.0f / lrow1;
    float* obase = out + (size_t)b * Sq * Dq + (size_t)h * HDq;
#pragma unroll
    for (int ni = 0; ni < 8; ni++) {
        const int c = ni * 8 + 2 * tq;
        float2 o0 = make_float2(Oacc[ni][0] * inv0, Oacc[ni][1] * inv0);
        float2 o1 = make_float2(Oacc[ni][2] * inv1, Oacc[ni][3] * inv1);
        *(float2*)(obase + (size_t)(q0 + r0) * Dq + c) = o0;
        *(float2*)(obase + (size_t)(q0 + r1) * Dq + c) = o1;
    }
}

// ---------------------------------------------------------------------------
extern "C" void kernel_launch(void* const* d_in, const int* in_sizes, int n_in,
                              void* d_out, int out_size)
{
    const float* x    = (const float*)d_in[0];
    const float* mask = (const float*)d_in[1];
    const float* Wqkv = (const float*)d_in[2];
    const float* bqkv = (const float*)d_in[3];
    const float* Wo   = (const float*)d_in[4];
    const float* bo   = (const float*)d_in[5];
    float* out = (float*)d_out;

    float* qkv  = nullptr;
    float* vals = nullptr;
    cudaGetSymbolAddress((void**)&qkv,  g_qkv);
    cudaGetSymbolAddress((void**)&vals, g_vals);

    // 1) QKV projection (epilogue rounds output to tf32 for flash raw copies)
    {
        dim3 grid((3 * Dq) / 128, (Bq * Sq) / 128);
        gemm_tf32_nt_bias<true><<<grid, 256>>>(Bq * Sq, 3 * Dq, Dq, x, Wqkv, bqkv, qkv);
    }

    // 2) Flash attention (tf32 mma, 53KB smem, 4 CTAs/SM, raw tile copies)
    {
        const int smem = (2 * 64 * QP + 64 * VP) * (int)sizeof(uint32_t); // 53248 B
        cudaFuncSetAttribute(flash_attn_tf32,
                             cudaFuncAttributeMaxDynamicSharedMemorySize, smem);
        dim3 grid(Sq / 64, Hq, Bq);
        flash_attn_tf32<<<grid, 128, smem>>>(qkv, mask, vals);
    }

    // 3) Output projection (plain fp32 epilogue)
    {
        dim3 grid(Dq / 128, (Bq * Sq) / 128);
        gemm_tf32_nt_bias<false><<<grid, 256>>>(Bq * Sq, Dq, Dq, vals, Wo, bo, out);
    }
}